// round 10
// baseline (speedup 1.0000x reference)
#include <cuda_runtime.h>
#include <cuda_fp16.h>

#define HH 128
#define WW 128
#define BB 64
#define OO 32
#define NPIX (HH * WW)
#define NBUILD 512                   // first 512 linear bids are builders (wave 1)
#define NCTAS (HH * OO)
#define TPB 256

// 8 MB quad tap table: g_Q[pix][lane(b-pair)] = {Ia, Ic, Ib, Id} as 4x half2
__device__ uint4 g_Q[NPIX * 32];
__device__ float4 g_aff[OO];
__device__ float2 g_off[OO];
__device__ unsigned g_done = 0;      // builders finished
__device__ unsigned g_pass = 0;      // CTAs past the barrier (for reset)

__global__ __launch_bounds__(TPB, 8) void fused_kernel(
    const float* __restrict__ X,
    const float* __restrict__ eps,
    const float* __restrict__ tmin,
    const float* __restrict__ tmax,
    float* __restrict__ out)
{
    __shared__ __half2 plane[WW][32];        // main: swizzled result plane (16 KB)
    __shared__ __half2 s2[2][33][33];        // build: staging tile (8.7 KB)
    __shared__ int s_go;

    const int tid  = threadIdx.x;
    const int lane = tid & 31;
    const int warp = tid >> 5;               // 0..7
    const int y = blockIdx.x;
    const int o = blockIdx.y;
    const unsigned bid = blockIdx.x + blockIdx.y * HH;   // linear, x-fastest

    // ================= build phase (first 512 bids, all in wave 1) =========
    if (bid < NBUILD) {
        if (bid == 0 && tid < OO) {          // affine setup rides on bid 0
            const int oo = tid;
            float th[7];
            #pragma unroll
            for (int i = 0; i < 7; i++) {
                const float mn = tmin[i];
                th[i] = fmaf(tmax[i] - mn, eps[oo * 7 + i], mn);
            }
            float s, c;
            sincosf(th[0], &s, &c);
            const float sx = th[1], sy = th[2], pX = th[3], pY = th[4], tx = th[5], ty = th[6];
            const float a00 = c * sx - s * pY;
            const float a01 = c * pX - s * sy;
            const float a10 = s * sx + c * pY;
            const float a11 = s * pX + c * sy;
            g_aff[oo] = make_float4(a00, a10, a01, a11);
            g_off[oo] = make_float2(63.5f * (tx + 1.0f - a00 - a01),
                                    63.5f * (ty + 1.0f - a10 - a11));
        }

        const int q  = o;                    // x-quadrant 0..3
        const int yn = min(y + 1, HH - 1);

        // stage rows (y, y+1), local cols [0,33), all 64 b. Unrolled -> 16 LDGs in flight.
        #pragma unroll
        for (int t = 0; t < 16; t++) {
            const int task = warp + t * 8;   // 0..127
            const int r = task >> 6;
            const int b = task & (BB - 1);
            const float* src = X + ((size_t)b * HH + (r ? yn : y)) * WW;
            __half* hp = reinterpret_cast<__half*>(&s2[r][0][b >> 1]) + (b & 1);
            const int gx = min(q * 32 + lane, WW - 1);
            hp[lane * 66] = __float2half(src[gx]);
            if (lane == 0) {
                const int gx2 = min(q * 32 + 32, WW - 1);
                hp[32 * 66] = __float2half(src[gx2]);
            }
        }
        __syncthreads();

        // emit quad records: warp handles xl = 4w..4w+3; lane = b-pair
        uint4* dst = g_Q + ((size_t)y * WW + q * 32) * 32;
        #pragma unroll
        for (int ii = 0; ii < 4; ii++) {
            const int xl = warp * 4 + ii;
            uint4 qq;
            qq.x = *reinterpret_cast<const unsigned*>(&s2[0][xl][lane]);
            qq.y = *reinterpret_cast<const unsigned*>(&s2[0][xl + 1][lane]);
            qq.z = *reinterpret_cast<const unsigned*>(&s2[1][xl][lane]);
            qq.w = *reinterpret_cast<const unsigned*>(&s2[1][xl + 1][lane]);
            dst[xl * 32 + lane] = qq;
        }
        __threadfence();                     // publish g_Q (+ g_aff) device-wide
        __syncthreads();
        if (tid == 0) atomicAdd(&g_done, 1u);
    }

    // ================= device barrier (replay-deterministic) ================
    if (tid == 0) {
        while (atomicAdd(&g_done, 0u) < NBUILD) __nanosleep(64);
        __threadfence();                     // acquire builders' writes
        const unsigned p = atomicAdd(&g_pass, 1u) + 1u;
        if (p == NCTAS) {                    // last CTA past barrier: reset for next replay
            g_done = 0u;
            __threadfence();
            g_pass = 0u;
        }
        s_go = 1;
    }
    __syncthreads();
    (void)s_go;

    // ================= main phase (all 4096 CTAs) ===========================
    const float4 A  = g_aff[o];
    const float2 Of = g_off[o];
    const float a00 = A.x, a10 = A.y, a01 = A.z, a11 = A.w;

    const float rowx = fmaf(a01, (float)y, Of.x);
    const float rowy = fmaf(a11, (float)y, Of.y);

    #pragma unroll 8
    for (int i = 0; i < 16; i++) {
        const int x = warp * 16 + i;

        const float cx = fminf(fmaxf(fmaf(a00, (float)x, rowx), 0.0f), 126.99999f);
        const float cy = fminf(fmaxf(fmaf(a10, (float)x, rowy), 0.0f), 126.99999f);
        const int x0 = (int)cx;
        const int y0 = (int)cy;
        const __half2 wx2 = __float2half2_rn(cx - (float)x0);
        const __half2 wy2 = __float2half2_rn(cy - (float)y0);

        // ONE LDG.128 fetches all 4 taps for this lane's b-pair
        const uint4 qv = g_Q[(unsigned)((y0 * WW + x0) * 32 + lane)];
        const __half2 Ia = *reinterpret_cast<const __half2*>(&qv.x);
        const __half2 Ic = *reinterpret_cast<const __half2*>(&qv.y);
        const __half2 Ib = *reinterpret_cast<const __half2*>(&qv.z);
        const __half2 Id = *reinterpret_cast<const __half2*>(&qv.w);

        const __half2 t0 = __hfma2(wx2, __hsub2(Ic, Ia), Ia);
        const __half2 t1 = __hfma2(wx2, __hsub2(Id, Ib), Ib);
        const __half2 r  = __hfma2(wy2, __hsub2(t1, t0), t0);

        plane[x][lane ^ (x & 31)] = r;       // bank permutation: conflict-free
    }

    __syncthreads();

    // writeout: warp w handles b-pairs p = 4w..4w+3; lane = x mod 32
    #pragma unroll
    for (int pp = 0; pp < 4; pp++) {
        const int p = warp * 4 + pp;         // b = 2p, 2p+1
        float* __restrict__ d0 = out + (size_t)(o * BB + 2 * p) * NPIX + y * WW;
        float* __restrict__ d1 = d0 + NPIX;
        #pragma unroll
        for (int j = 0; j < 4; j++) {
            const int x = j * 32 + lane;
            const float2 v = __half22float2(plane[x][p ^ lane]); // conflict-free
            d0[x] = v.x;
            d1[x] = v.y;
        }
    }
}

extern "C" void kernel_launch(void* const* d_in, const int* in_sizes, int n_in,
                              void* d_out, int out_size)
{
    const float* X    = (const float*)d_in[0];
    const float* eps  = (const float*)d_in[1];
    const float* tmin = (const float*)d_in[2];
    const float* tmax = (const float*)d_in[3];
    float* out = (float*)d_out;

    dim3 grid(HH, OO);                       // 4096 CTAs, builders = first 512 bids
    fused_kernel<<<grid, TPB>>>(X, eps, tmin, tmax, out);
}